// round 14
// baseline (speedup 1.0000x reference)
#include <cuda_runtime.h>
#include <cuda_fp16.h>
#include <cstdint>

// ---------------------------------------------------------------------------
// Problem constants
// ---------------------------------------------------------------------------
#define D       64
#define KTOT    2048
#define NROWS   65536
#define M_BLK   256                  // rows per block (32 per warp, 8 warps)
#define NSUB    64
#define NSUBS   (KTOT / NSUB)        // 32
#define NBLOCKS (NROWS / M_BLK)      // 256

// Output layout (concatenated fp32)
#define OFF_IDX  ((size_t)NROWS * D)
#define OFF_FLAT ((size_t)NROWS * D + NROWS)

// smem layout (bytes). A row = [X0] 128B, stride 144 (144%128==16 ->
// conflict-free ldmatrix). B row = [E0|E1] 256B, stride 272.
#define SA_A       144
#define SA_B       272
#define SM_A       0
#define SM_B0      (M_BLK * SA_A)                   // 36864
#define SM_B1      (SM_B0 + 64 * SA_B)              // 54272
#define SM_NH0     (SM_B1 + 64 * SA_B)              // 71680
#define SM_NH1     (SM_NH0 + 256)                   // 71936
#define SM_XN      (SM_NH1 + 256)                   // 72192 (256 floats ||x1||^2)
#define SMEM_TOTAL (SM_XN + 1024)                   // 73216 -> 2 CTAs/SM

// ---------------------------------------------------------------------------
// Device scratch (no cudaMalloc allowed)
// ---------------------------------------------------------------------------
__device__ unsigned g_B[KTOT * 64];            // B' [E0|E1] packed fp16x2 (L2)
__device__ float    g_nh[KTOT];                // -0.5*||e_k||^2
__device__ float    g_e0max = 0.f;             // max_k ||E0_k|| (monotone across replays)
__device__ int      g_bi[NROWS];
__device__ int      g_rlist[NROWS];
__device__ int      g_rcnt;
__device__ unsigned long long g_bm[NROWS];     // packed (score,~idx); 0 = not rescued

// ---------------------------------------------------------------------------
// PTX helpers (all baseline sm_80+, safe for compute_103)
// ---------------------------------------------------------------------------
__device__ __forceinline__ uint32_t smem_u32(const void* p) {
    uint32_t a;
    asm("{ .reg .u64 t; cvta.to.shared.u64 t, %1; cvt.u32.u64 %0, t; }" : "=r"(a) : "l"(p));
    return a;
}
__device__ __forceinline__ void cpa16(uint32_t dst, const void* src) {
    asm volatile("cp.async.cg.shared.global [%0], [%1], 16;" :: "r"(dst), "l"(src));
}
#define CP_COMMIT() asm volatile("cp.async.commit_group;" ::: "memory")
#define CP_WAIT0()  asm volatile("cp.async.wait_group 0;" ::: "memory")

#define LDSM4(r0, r1, r2, r3, addr)                                           \
    asm volatile("ldmatrix.sync.aligned.m8n8.x4.shared.b16 {%0,%1,%2,%3}, [%4];" \
                 : "=r"(r0), "=r"(r1), "=r"(r2), "=r"(r3) : "r"(addr))

#define MMA16816(c, a0, a1, a2, a3, b0, b1)                                   \
    asm volatile("mma.sync.aligned.m16n8k16.row.col.f32.f16.f16.f32 "         \
                 "{%0,%1,%2,%3}, {%4,%5,%6,%7}, {%8,%9}, {%0,%1,%2,%3};"      \
                 : "+f"((c)[0]), "+f"((c)[1]), "+f"((c)[2]), "+f"((c)[3])     \
                 : "r"(a0), "r"(a1), "r"(a2), "r"(a3), "r"(b0), "r"(b1))

// ---------------------------------------------------------------------------
// Exact 2-way fp16 split: x = f0 + f1 + O(2^-22 |x|)
// ---------------------------------------------------------------------------
__device__ __forceinline__ void split2h(float x, unsigned short& s0, unsigned short& s1) {
    __half h0 = __float2half_rn(x);
    float r = x - __half2float(h0);            // exact (Sterbenz)
    __half h1 = __float2half_rn(r);
    s0 = __half_as_ushort(h0);
    s1 = __half_as_ushort(h1);
}

// ---------------------------------------------------------------------------
// Prep (fused): B' rows = [E0 | E1], nh, E0-norm max, rcnt reset.
// One warp == one codebook row.
// ---------------------------------------------------------------------------
__global__ void vq_split_e(const float* __restrict__ emb) {
    int i = blockIdx.x * blockDim.x + threadIdx.x;   // KTOT*32 threads
    if (i == 0) g_rcnt = 0;
    float2 v = reinterpret_cast<const float2*>(emb)[i];
    unsigned short a0, a1, b0, b1;
    split2h(v.x, a0, a1);
    split2h(v.y, b0, b1);
    int k = i >> 5, d2 = i & 31;
    unsigned* base = g_B + (size_t)k * 64;
    base[d2]      = (unsigned)a0 | ((unsigned)b0 << 16);   // E0
    base[32 + d2] = (unsigned)a1 | ((unsigned)b1 << 16);   // E1

    // warp reductions: ||e||^2 (for nh) and ||E0||^2 (for error bound)
    float p  = fmaf(v.x, v.x, v.y * v.y);
    float e0x = __half2float(__ushort_as_half(a0));
    float e0y = __half2float(__ushort_as_half(b0));
    float p0 = fmaf(e0x, e0x, e0y * e0y);
#pragma unroll
    for (int m = 16; m >= 1; m >>= 1) {
        p  += __shfl_xor_sync(0xffffffffu, p, m);
        p0 += __shfl_xor_sync(0xffffffffu, p0, m);
    }
    if (d2 == 0) {
        g_nh[k] = -0.5f * p;
        atomicMax((int*)&g_e0max, __float_as_int(sqrtf(p0)));  // positive floats
    }
}

// ---------------------------------------------------------------------------
// top-2 update / merge helpers
// ---------------------------------------------------------------------------
__device__ __forceinline__ void upd(float& b1, float& b2, int& i1, float v, int idx) {
    if (v > b1) { b2 = b1; b1 = v; i1 = idx; }
    else        { b2 = fmaxf(b2, v); }
}
__device__ __forceinline__ void mergepair(float& b1, float& b2, int& i1, unsigned m) {
    float ob1 = __shfl_xor_sync(0xffffffffu, b1, m);
    float ob2 = __shfl_xor_sync(0xffffffffu, b2, m);
    int   oi1 = __shfl_xor_sync(0xffffffffu, i1, m);
    if (ob1 > b1 || (ob1 == b1 && oi1 < i1)) { b2 = fmaxf(b1, ob2); b1 = ob1; i1 = oi1; }
    else                                     { b2 = fmaxf(b2, ob1); }
}

// ---------------------------------------------------------------------------
// Main kernel: 2-term GEMM  score~ = X0.E0 + X0.E1 + nh.
// Dropped X1.(E0+..) term bounded per row by ||x1||*max||E0|| (exact norms).
// ---------------------------------------------------------------------------
__global__ void __launch_bounds__(256, 2) vq_mma_kernel(const float* __restrict__ inp) {
    extern __shared__ __align__(16) char smem[];
    const uint32_t SB  = smem_u32(smem);
    const int tid  = threadIdx.x;
    const int lane = tid & 31;
    const int wid  = tid >> 5;
    const int row0blk = blockIdx.x * M_BLK;

    const uint32_t smA = SB + SM_A;
    const uint32_t smB[2] = { SB + SM_B0, SB + SM_B1 };
    float* nhbuf[2] = { (float*)(smem + SM_NH0), (float*)(smem + SM_NH1) };
    float* sxn = (float*)(smem + SM_XN);       // per-row ||x1||^2

    // ---- prologue: prefetch B subtile 0 (async), split A (X0 only) + norms ----
    {
        const char* gB = (const char*)g_B;
#pragma unroll
        for (int i = tid; i < 64 * 16; i += 256) {
            int r = i >> 4, c = i & 15;
            cpa16(smB[0] + r * SA_B + c * 16, gB + (size_t)r * 256 + c * 16);
        }
        if (tid < 64) nhbuf[0][tid] = g_nh[tid];
        CP_COMMIT();

        // Each warp iteration handles one whole row (lane = d2 chunk).
        const float2* xin = reinterpret_cast<const float2*>(inp + (size_t)row0blk * D);
#pragma unroll
        for (int i = tid; i < M_BLK * 32; i += 256) {
            int r = i >> 5, d2 = i & 31;
            float2 v = xin[i];
            unsigned short a0, a1, b0, b1;
            split2h(v.x, a0, a1);
            split2h(v.y, b0, b1);
            reinterpret_cast<unsigned*>(smem + SM_A + r * SA_A)[d2] =
                (unsigned)a0 | ((unsigned)b0 << 16);        // X0 plane
            // residual norm: exact x1 components
            float r1x = v.x - __half2float(__ushort_as_half(a0));
            float r1y = v.y - __half2float(__ushort_as_half(b0));
            float p = fmaf(r1x, r1x, r1y * r1y);
#pragma unroll
            for (int m = 16; m >= 1; m >>= 1) p += __shfl_xor_sync(0xffffffffu, p, m);
            if (d2 == 0) sxn[r] = p;
        }
        CP_WAIT0();
        __syncthreads();
    }

    const uint32_t aAddr0 = smA + (wid * 32 + (lane & 15)) * SA_A + (lane >> 4) * 16;
    const uint32_t aAddr1 = aAddr0 + 16 * SA_A;
    const int q       = lane >> 3;
    const int brow    = ((q >> 1) * 8) + (lane & 7);
    const uint32_t bk = (q & 1) * 16;

    float b1r[4], b2r[4];
    int   i1r[4];
#pragma unroll
    for (int r = 0; r < 4; r++) { b1r[r] = b2r[r] = -3.402823466e+38f; i1r[r] = 0; }

    for (int s = 0; s < NSUBS; s++) {
        const int buf = s & 1;
        if (s + 1 < NSUBS) {
            const char* gB = (const char*)(g_B + (size_t)(s + 1) * 64 * 64);
#pragma unroll
            for (int i = tid; i < 64 * 16; i += 256) {
                int r = i >> 4, c = i & 15;
                cpa16(smB[buf ^ 1] + r * SA_B + c * 16, gB + (size_t)r * 256 + c * 16);
            }
            if (tid < 64) nhbuf[buf ^ 1][tid] = g_nh[(s + 1) * 64 + tid];
            CP_COMMIT();
        }

        float c[2][8][4];
#pragma unroll
        for (int mt = 0; mt < 2; mt++)
#pragma unroll
            for (int j = 0; j < 8; j++)
                c[mt][j][0] = c[mt][j][1] = c[mt][j][2] = c[mt][j][3] = 0.f;

        const uint32_t bb = smB[buf];
#pragma unroll
        for (int ks = 0; ks < 4; ks++) {
            const uint32_t ko = ks * 32;
            uint32_t p0, p1, p2, p3, p4, p5, p6, p7;       // X0 m0, m1
            LDSM4(p0, p1, p2, p3, aAddr0 + ko);
            LDSM4(p4, p5, p6, p7, aAddr1 + ko);
#pragma unroll
            for (int t = 0; t < 4; t++) {
                const uint32_t brbase = bb + (t * 16 + brow) * SA_B + bk;
                uint32_t r0, r1, r2, r3;                   // E0 frag
                LDSM4(r0, r1, r2, r3, brbase + ko);
                MMA16816(c[0][2 * t],     p0, p1, p2, p3, r0, r1);
                MMA16816(c[0][2 * t + 1], p0, p1, p2, p3, r2, r3);
                MMA16816(c[1][2 * t],     p4, p5, p6, p7, r0, r1);
                MMA16816(c[1][2 * t + 1], p4, p5, p6, p7, r2, r3);
                uint32_t s0, s1, s2, s3;                   // E1 frag
                LDSM4(s0, s1, s2, s3, brbase + 128 + ko);
                MMA16816(c[0][2 * t],     p0, p1, p2, p3, s0, s1);
                MMA16816(c[0][2 * t + 1], p0, p1, p2, p3, s2, s3);
                MMA16816(c[1][2 * t],     p4, p5, p6, p7, s0, s1);
                MMA16816(c[1][2 * t + 1], p4, p5, p6, p7, s2, s3);
            }
        }

        const float* snh = nhbuf[buf];
        const int cb = s * NSUB;
#pragma unroll
        for (int j = 0; j < 8; j++) {
            const int lc = j * 8 + 2 * (lane & 3);
            const float nh0 = snh[lc], nh1 = snh[lc + 1];
            const int gi = cb + lc;
            upd(b1r[0], b2r[0], i1r[0], c[0][j][0] + nh0, gi);
            upd(b1r[0], b2r[0], i1r[0], c[0][j][1] + nh1, gi + 1);
            upd(b1r[1], b2r[1], i1r[1], c[0][j][2] + nh0, gi);
            upd(b1r[1], b2r[1], i1r[1], c[0][j][3] + nh1, gi + 1);
            upd(b1r[2], b2r[2], i1r[2], c[1][j][0] + nh0, gi);
            upd(b1r[2], b2r[2], i1r[2], c[1][j][1] + nh1, gi + 1);
            upd(b1r[3], b2r[3], i1r[3], c[1][j][2] + nh0, gi);
            upd(b1r[3], b2r[3], i1r[3], c[1][j][3] + nh1, gi + 1);
        }

        if (s + 1 < NSUBS) {
            CP_WAIT0();
            __syncthreads();
        }
    }

#pragma unroll
    for (int r = 0; r < 4; r++) {
        mergepair(b1r[r], b2r[r], i1r[r], 1);
        mergepair(b1r[r], b2r[r], i1r[r], 2);
    }

    if ((lane & 3) == 0) {
        const float e0max = g_e0max;
        const int baseg = row0blk + wid * 32 + (lane >> 2);
        const int basel = wid * 32 + (lane >> 2);
        const int rofs[4] = { 0, 8, 16, 24 };
#pragma unroll
        for (int r = 0; r < 4; r++) {
            const int row = baseg + rofs[r];
            g_bi[row] = i1r[r];
            g_bm[row] = 0ull;                     // sentinel: 0 = not rescued
            // per-row rigorous bound on dropped X1 term + fp noise margin
            const float berr = sqrtf(sxn[basel + rofs[r]]) * e0max + 5e-4f;
            if (b1r[r] - b2r[r] < 2.0f * berr) {
                int p = atomicAdd(&g_rcnt, 1);
                g_rlist[p] = row;
            }
        }
    }
}

// ---------------------------------------------------------------------------
// Rescue v2 (coalesced): task = (flagged row, 512-code chunk).
// lane = (code-octet cq, dim-quarter q): warp instrs touch 16 lines (was 32).
// Winner via atomicMax on monotone-packed (score, ~idx) u64.
// ---------------------------------------------------------------------------
#define RES_CHUNK  512
#define RES_BLOCKS 296
__global__ void __launch_bounds__(256)
vq_rescue_kernel(const float* __restrict__ inp, const float* __restrict__ emb) {
    const int lane  = threadIdx.x & 31;
    const int gw    = (blockIdx.x * blockDim.x + threadIdx.x) >> 5;
    const int nw    = RES_BLOCKS * 256 / 32;
    const int ntask = g_rcnt * (KTOT / RES_CHUNK);   // cnt * 4

    const int cq = lane >> 2;     // code within octet (0..7)
    const int q  = lane & 3;      // dim quarter (0..3): dims q*16..q*16+15

    for (int t = gw; t < ntask; t += nw) {
        const int row = g_rlist[t >> 2];
        const int k0  = (t & 3) * RES_CHUNK;

        // this lane's x quarter (16 dims = 4 float4)
        float4 x[4];
        const float4* xr = reinterpret_cast<const float4*>(inp + (size_t)row * D) + q * 4;
#pragma unroll
        for (int j = 0; j < 4; j++) x[j] = xr[j];

        unsigned long long key = 0ull;
        for (int g = 0; g < RES_CHUNK / 8; g++) {
            const int k = k0 + g * 8 + cq;
            const float4* er = reinterpret_cast<const float4*>(emb + (size_t)k * D) + q * 4;
            float d0 = 0.f, d1 = 0.f, d2 = 0.f, d3 = 0.f;
#pragma unroll
            for (int j = 0; j < 4; j++) {
                float4 e = er[j];
                d0 = fmaf(x[j].x, e.x, d0);
                d1 = fmaf(x[j].y, e.y, d1);
                d2 = fmaf(x[j].z, e.z, d2);
                d3 = fmaf(x[j].w, e.w, d3);
            }
            float p = (d0 + d1) + (d2 + d3);
            // sum the 4 quarters (lanes differing in low 2 bits)
            p += __shfl_xor_sync(0xffffffffu, p, 1);
            p += __shfl_xor_sync(0xffffffffu, p, 2);
            float sc = p + g_nh[k];
            unsigned u = __float_as_uint(sc);
            u = (u & 0x80000000u) ? ~u : (u | 0x80000000u);   // monotone map
            unsigned long long pk = ((unsigned long long)u << 32) | (unsigned)(~k);
            key = (pk > key) ? pk : key;
        }
#pragma unroll
        for (int m = 16; m >= 1; m >>= 1) {
            unsigned long long ok = __shfl_xor_sync(0xffffffffu, key, m);
            key = (ok > key) ? ok : key;
        }
        if (lane == 0) atomicMax(&g_bm[row], key);
    }
}

// ---------------------------------------------------------------------------
// Combine: 8 threads/row, 2 float4 chunks per thread per stream.
// Rescue winners decoded inline from g_bm (nonzero = rescued).
// ---------------------------------------------------------------------------
__global__ void __launch_bounds__(256)
vq_combine_kernel(const float* __restrict__ inp,
                  const float* __restrict__ emb,
                  float* __restrict__ out) {
    const int t   = blockIdx.x * blockDim.x + threadIdx.x;   // NROWS*8
    const int row = t >> 3;
    const int c   = t & 7;

    const unsigned long long key = g_bm[row];
    const int bi = key ? ((int)(~(unsigned)(key & 0xFFFFFFFFull)) & (KTOT - 1))
                       : g_bi[row];

    const float4* qv = reinterpret_cast<const float4*>(emb + (size_t)bi * D);
    float4* oq = reinterpret_cast<float4*>(out + (size_t)row * D);
    oq[c]     = qv[c];
    oq[c + 8] = qv[c + 8];

    const float4* xi = reinterpret_cast<const float4*>(inp + (size_t)row * D);
    float4* of = reinterpret_cast<float4*>(out + OFF_FLAT + (size_t)row * D);
    of[c]     = xi[c];
    of[c + 8] = xi[c + 8];

    if (c == 0) out[OFF_IDX + row] = (float)bi;
}

// ---------------------------------------------------------------------------
extern "C" void kernel_launch(void* const* d_in, const int* in_sizes, int n_in,
                              void* d_out, int out_size) {
    const float* inp = (const float*)d_in[0];   // [64,32,32,64] fp32
    const float* emb = (const float*)d_in[1];   // [2048,64]     fp32
    float* out = (float*)d_out;

    static int smem_set = 0;
    if (!smem_set) {
        cudaFuncSetAttribute(vq_mma_kernel,
                             cudaFuncAttributeMaxDynamicSharedMemorySize, SMEM_TOTAL);
        smem_set = 1;
    }

    vq_split_e<<<KTOT * 32 / 256, 256>>>(emb);
    vq_mma_kernel<<<NBLOCKS, 256, SMEM_TOTAL>>>(inp);
    vq_rescue_kernel<<<RES_BLOCKS, 256>>>(inp, emb);
    vq_combine_kernel<<<NROWS * 8 / 256, 256>>>(inp, emb, out);
}

// round 15
// speedup vs baseline: 1.4870x; 1.4870x over previous
#include <cuda_runtime.h>
#include <cuda_fp16.h>
#include <cstdint>

// ---------------------------------------------------------------------------
// Problem constants
// ---------------------------------------------------------------------------
#define D       64
#define KTOT    2048
#define NROWS   65536
#define M_BLK   256                  // rows per block (32 per warp, 8 warps)
#define NSUB    64
#define NSUBS   (KTOT / NSUB)        // 32 total; 16 per K-half
#define KSPLIT  2
#define NBLOCKS (NROWS / M_BLK * KSPLIT)   // 512
// fp16 2-term split: dropped X1*E1 <= 2^-22*||x||*||e|| ~ 1.6e-5; plus fp32
// accumulation-order noise ~1e-5. THRESH = 2e-4 keeps >=4x margin.
#define THRESH  2.0e-4f

// Output layout (concatenated fp32)
#define OFF_IDX  ((size_t)NROWS * D)
#define OFF_FLAT ((size_t)NROWS * D + NROWS)

// smem layout (bytes); row stride 272 (conflict-free ldmatrix banking).
// A row = [X0|X1] 256B; B row = [E0|E1] 256B.
#define SA_ROW     272
#define SM_A       0
#define SM_B0      (M_BLK * SA_ROW)                 // 69632
#define SM_B1      (SM_B0 + 64 * SA_ROW)            // 87040
#define SM_NH0     (SM_B1 + 64 * SA_ROW)            // 104448
#define SM_NH1     (SM_NH0 + 256)                   // 104704
#define SMEM_TOTAL (SM_NH1 + 256)                   // 104960 -> 2 CTAs/SM

// ---------------------------------------------------------------------------
// Device scratch (no cudaMalloc allowed)
// ---------------------------------------------------------------------------
__device__ unsigned g_B[KTOT * 64];            // B' [E0|E1] packed fp16x2 (L2)
__device__ float    g_nh[KTOT];                // -0.5*||e_k||^2
__device__ float    g_pb1[KSPLIT * NROWS];     // partial best score
__device__ float    g_pb2[KSPLIT * NROWS];     // partial runner-up score
__device__ int      g_pi [KSPLIT * NROWS];     // partial best index
__device__ int      g_bi[NROWS];
__device__ int      g_rlist[NROWS];
__device__ int      g_rcnt;
__device__ unsigned long long g_bm[NROWS];     // packed (score,~idx); 0 = not rescued

// ---------------------------------------------------------------------------
// PTX helpers (all baseline sm_80+, safe for compute_103)
// ---------------------------------------------------------------------------
__device__ __forceinline__ uint32_t smem_u32(const void* p) {
    uint32_t a;
    asm("{ .reg .u64 t; cvta.to.shared.u64 t, %1; cvt.u32.u64 %0, t; }" : "=r"(a) : "l"(p));
    return a;
}
__device__ __forceinline__ void cpa16(uint32_t dst, const void* src) {
    asm volatile("cp.async.cg.shared.global [%0], [%1], 16;" :: "r"(dst), "l"(src));
}
#define CP_COMMIT() asm volatile("cp.async.commit_group;" ::: "memory")
#define CP_WAIT0()  asm volatile("cp.async.wait_group 0;" ::: "memory")

#define LDSM4(r0, r1, r2, r3, addr)                                           \
    asm volatile("ldmatrix.sync.aligned.m8n8.x4.shared.b16 {%0,%1,%2,%3}, [%4];" \
                 : "=r"(r0), "=r"(r1), "=r"(r2), "=r"(r3) : "r"(addr))

#define MMA16816(c, a0, a1, a2, a3, b0, b1)                                   \
    asm volatile("mma.sync.aligned.m16n8k16.row.col.f32.f16.f16.f32 "         \
                 "{%0,%1,%2,%3}, {%4,%5,%6,%7}, {%8,%9}, {%0,%1,%2,%3};"      \
                 : "+f"((c)[0]), "+f"((c)[1]), "+f"((c)[2]), "+f"((c)[3])     \
                 : "r"(a0), "r"(a1), "r"(a2), "r"(a3), "r"(b0), "r"(b1))

// ---------------------------------------------------------------------------
// Exact 2-way fp16 split: x = f0 + f1 + O(2^-22 |x|)
// ---------------------------------------------------------------------------
__device__ __forceinline__ void split2h(float x, unsigned short& s0, unsigned short& s1) {
    __half h0 = __float2half_rn(x);
    float r = x - __half2float(h0);            // exact (Sterbenz)
    __half h1 = __float2half_rn(r);
    s0 = __half_as_ushort(h0);
    s1 = __half_as_ushort(h1);
}

// ---------------------------------------------------------------------------
// Prep (fused): B' rows = [E0 | E1], nh, rcnt reset. One warp == one code row.
// ---------------------------------------------------------------------------
__global__ void vq_split_e(const float* __restrict__ emb) {
    int i = blockIdx.x * blockDim.x + threadIdx.x;   // KTOT*32 threads
    if (i == 0) g_rcnt = 0;
    float2 v = reinterpret_cast<const float2*>(emb)[i];
    unsigned short a0, a1, b0, b1;
    split2h(v.x, a0, a1);
    split2h(v.y, b0, b1);
    int k = i >> 5, d2 = i & 31;
    unsigned* base = g_B + (size_t)k * 64;
    base[d2]      = (unsigned)a0 | ((unsigned)b0 << 16);   // E0
    base[32 + d2] = (unsigned)a1 | ((unsigned)b1 << 16);   // E1

    float p = fmaf(v.x, v.x, v.y * v.y);
#pragma unroll
    for (int m = 16; m >= 1; m >>= 1) p += __shfl_xor_sync(0xffffffffu, p, m);
    if (d2 == 0) g_nh[k] = -0.5f * p;
}

// ---------------------------------------------------------------------------
// top-2 update / merge helpers
// ---------------------------------------------------------------------------
__device__ __forceinline__ void upd(float& b1, float& b2, int& i1, float v, int idx) {
    if (v > b1) { b2 = b1; b1 = v; i1 = idx; }
    else        { b2 = fmaxf(b2, v); }
}
__device__ __forceinline__ void mergepair(float& b1, float& b2, int& i1, unsigned m) {
    float ob1 = __shfl_xor_sync(0xffffffffu, b1, m);
    float ob2 = __shfl_xor_sync(0xffffffffu, b2, m);
    int   oi1 = __shfl_xor_sync(0xffffffffu, i1, m);
    if (ob1 > b1 || (ob1 == b1 && oi1 < i1)) { b2 = fmaxf(b1, ob2); b1 = ob1; i1 = oi1; }
    else                                     { b2 = fmaxf(b2, ob1); }
}

// ---------------------------------------------------------------------------
// Main kernel (K-split): block b -> row chunk (b>>1), K-half (b&1).
// 3-term GEMM score~ = X0.E0 + X1.E0 + X0.E1 + nh over 16 subtiles.
// Grid 512 over 296 residency slots -> scheduler load-balances the tail.
// ---------------------------------------------------------------------------
__global__ void __launch_bounds__(256, 2) vq_mma_kernel(const float* __restrict__ inp) {
    extern __shared__ __align__(16) char smem[];
    const uint32_t SB  = smem_u32(smem);
    const int tid  = threadIdx.x;
    const int lane = tid & 31;
    const int wid  = tid >> 5;
    const int half = blockIdx.x & 1;
    const int row0blk = (blockIdx.x >> 1) * M_BLK;
    const int s0 = half * (NSUBS / KSPLIT);          // 0 or 16
    const int s1 = s0 + (NSUBS / KSPLIT);

    const uint32_t smA = SB + SM_A;
    const uint32_t smB[2] = { SB + SM_B0, SB + SM_B1 };
    float* nhbuf[2] = { (float*)(smem + SM_NH0), (float*)(smem + SM_NH1) };

    // ---- prologue: prefetch first B subtile (async), split A into smem ----
    {
        const char* gB = (const char*)(g_B + (size_t)s0 * 64 * 64);
#pragma unroll
        for (int i = tid; i < 64 * 16; i += 256) {
            int r = i >> 4, c = i & 15;
            cpa16(smB[0] + r * SA_ROW + c * 16, gB + (size_t)r * 256 + c * 16);
        }
        if (tid < 64) nhbuf[0][tid] = g_nh[s0 * 64 + tid];
        CP_COMMIT();

        const float2* xin = reinterpret_cast<const float2*>(inp + (size_t)row0blk * D);
#pragma unroll
        for (int i = tid; i < M_BLK * 32; i += 256) {
            int r = i >> 5, d2 = i & 31;
            float2 v = xin[i];
            unsigned short a0, a1, b0, b1;
            split2h(v.x, a0, a1);
            split2h(v.y, b0, b1);
            unsigned* rowp = reinterpret_cast<unsigned*>(smem + SM_A + r * SA_ROW);
            rowp[d2]      = (unsigned)a0 | ((unsigned)b0 << 16);   // X0
            rowp[32 + d2] = (unsigned)a1 | ((unsigned)b1 << 16);   // X1
        }
        CP_WAIT0();
        __syncthreads();
    }

    const uint32_t aAddr0 = smA + (wid * 32 + (lane & 15)) * SA_ROW + (lane >> 4) * 16;
    const uint32_t aAddr1 = aAddr0 + 16 * SA_ROW;
    const int q       = lane >> 3;
    const int brow    = ((q >> 1) * 8) + (lane & 7);
    const uint32_t bk = (q & 1) * 16;

    float b1r[4], b2r[4];
    int   i1r[4];
#pragma unroll
    for (int r = 0; r < 4; r++) { b1r[r] = b2r[r] = -3.402823466e+38f; i1r[r] = s0 * NSUB; }

    for (int s = s0; s < s1; s++) {
        const int buf = (s - s0) & 1;
        if (s + 1 < s1) {
            const char* gB = (const char*)(g_B + (size_t)(s + 1) * 64 * 64);
#pragma unroll
            for (int i = tid; i < 64 * 16; i += 256) {
                int r = i >> 4, c = i & 15;
                cpa16(smB[buf ^ 1] + r * SA_ROW + c * 16, gB + (size_t)r * 256 + c * 16);
            }
            if (tid < 64) nhbuf[buf ^ 1][tid] = g_nh[(s + 1) * 64 + tid];
            CP_COMMIT();
        }

        float c[2][8][4];
#pragma unroll
        for (int mt = 0; mt < 2; mt++)
#pragma unroll
            for (int j = 0; j < 8; j++)
                c[mt][j][0] = c[mt][j][1] = c[mt][j][2] = c[mt][j][3] = 0.f;

        const uint32_t bb = smB[buf];
#pragma unroll
        for (int ks = 0; ks < 4; ks++) {
            const uint32_t ko = ks * 32;
            uint32_t p0, p1, p2, p3, p4, p5, p6, p7;       // X0 m0, m1
            uint32_t q0, q1, q2, q3, q4, q5, q6, q7;       // X1 m0, m1
            LDSM4(p0, p1, p2, p3, aAddr0 + ko);
            LDSM4(p4, p5, p6, p7, aAddr1 + ko);
            LDSM4(q0, q1, q2, q3, aAddr0 + 128 + ko);
            LDSM4(q4, q5, q6, q7, aAddr1 + 128 + ko);
#pragma unroll
            for (int t = 0; t < 4; t++) {
                const uint32_t brbase = bb + (t * 16 + brow) * SA_ROW + bk;
                uint32_t r0, r1, r2, r3;                   // E0 frag
                LDSM4(r0, r1, r2, r3, brbase + ko);
                MMA16816(c[0][2 * t],     p0, p1, p2, p3, r0, r1);
                MMA16816(c[0][2 * t + 1], p0, p1, p2, p3, r2, r3);
                MMA16816(c[1][2 * t],     p4, p5, p6, p7, r0, r1);
                MMA16816(c[1][2 * t + 1], p4, p5, p6, p7, r2, r3);
                MMA16816(c[0][2 * t],     q0, q1, q2, q3, r0, r1);
                MMA16816(c[0][2 * t + 1], q0, q1, q2, q3, r2, r3);
                MMA16816(c[1][2 * t],     q4, q5, q6, q7, r0, r1);
                MMA16816(c[1][2 * t + 1], q4, q5, q6, q7, r2, r3);
                uint32_t s0r, s1r, s2r, s3r;               // E1 frag
                LDSM4(s0r, s1r, s2r, s3r, brbase + 128 + ko);
                MMA16816(c[0][2 * t],     p0, p1, p2, p3, s0r, s1r);
                MMA16816(c[0][2 * t + 1], p0, p1, p2, p3, s2r, s3r);
                MMA16816(c[1][2 * t],     p4, p5, p6, p7, s0r, s1r);
                MMA16816(c[1][2 * t + 1], p4, p5, p6, p7, s2r, s3r);
            }
        }

        const float* snh = nhbuf[buf];
        const int cb = s * NSUB;
#pragma unroll
        for (int j = 0; j < 8; j++) {
            const int lc = j * 8 + 2 * (lane & 3);
            const float nh0 = snh[lc], nh1 = snh[lc + 1];
            const int gi = cb + lc;
            upd(b1r[0], b2r[0], i1r[0], c[0][j][0] + nh0, gi);
            upd(b1r[0], b2r[0], i1r[0], c[0][j][1] + nh1, gi + 1);
            upd(b1r[1], b2r[1], i1r[1], c[0][j][2] + nh0, gi);
            upd(b1r[1], b2r[1], i1r[1], c[0][j][3] + nh1, gi + 1);
            upd(b1r[2], b2r[2], i1r[2], c[1][j][0] + nh0, gi);
            upd(b1r[2], b2r[2], i1r[2], c[1][j][1] + nh1, gi + 1);
            upd(b1r[3], b2r[3], i1r[3], c[1][j][2] + nh0, gi);
            upd(b1r[3], b2r[3], i1r[3], c[1][j][3] + nh1, gi + 1);
        }

        if (s + 1 < s1) {
            CP_WAIT0();
            __syncthreads();
        }
    }

#pragma unroll
    for (int r = 0; r < 4; r++) {
        mergepair(b1r[r], b2r[r], i1r[r], 1);
        mergepair(b1r[r], b2r[r], i1r[r], 2);
    }

    if ((lane & 3) == 0) {
        const int base = row0blk + wid * 32 + (lane >> 2);
        const int rofs[4] = { 0, 8, 16, 24 };
        float* pb1 = g_pb1 + (size_t)half * NROWS;
        float* pb2 = g_pb2 + (size_t)half * NROWS;
        int*   pi  = g_pi  + (size_t)half * NROWS;
#pragma unroll
        for (int r = 0; r < 4; r++) {
            const int row = base + rofs[r];
            pb1[row] = b1r[r];
            pb2[row] = b2r[r];
            pi[row]  = i1r[r];
        }
    }
}

// ---------------------------------------------------------------------------
// Merge halves: pick winner (tie -> half 0 = lower index), compute gap,
// flag close rows for rescue, init g_bm sentinel.
// ---------------------------------------------------------------------------
__global__ void __launch_bounds__(256)
vq_merge_kernel() {
    const int row = blockIdx.x * blockDim.x + threadIdx.x;
    const float a1 = g_pb1[row],          a2 = g_pb2[row];
    const float c1 = g_pb1[NROWS + row],  c2 = g_pb2[NROWS + row];
    const int   ai = g_pi[row],           ci = g_pi[NROWS + row];

    float m1, m2;
    int bi;
    if (c1 > a1) { m1 = c1; bi = ci; m2 = fmaxf(a1, c2); }
    else         { m1 = a1; bi = ai; m2 = fmaxf(c1, a2); }  // tie -> half 0

    g_bi[row] = bi;
    g_bm[row] = 0ull;
    if (m1 - m2 < THRESH) {
        int p = atomicAdd(&g_rcnt, 1);
        g_rlist[p] = row;
    }
}

// ---------------------------------------------------------------------------
// Rescue: exact fp32 rescan, task = (flagged row, 256-code chunk).
// ---------------------------------------------------------------------------
#define RES_CHUNK  256
#define RES_BLOCKS 148
__global__ void __launch_bounds__(256)
vq_rescue_kernel(const float* __restrict__ inp, const float* __restrict__ emb) {
    const int lane  = threadIdx.x & 31;
    const int gw    = (blockIdx.x * blockDim.x + threadIdx.x) >> 5;
    const int nw    = RES_BLOCKS * 256 / 32;
    const int ntask = g_rcnt * (KTOT / RES_CHUNK);

    for (int t = gw; t < ntask; t += nw) {
        const int row = g_rlist[t >> 3];
        const int k0  = (t & 7) * RES_CHUNK;

        float4 x[16];
        const float4* xr = reinterpret_cast<const float4*>(inp + (size_t)row * D);
#pragma unroll
        for (int j = 0; j < 16; j++) x[j] = xr[j];

        unsigned long long key = 0ull;
        for (int k = k0 + lane; k < k0 + RES_CHUNK; k += 32) {
            const float4* er = reinterpret_cast<const float4*>(emb + (size_t)k * D);
            float d0 = 0.f, d1 = 0.f, d2 = 0.f, d3 = 0.f;
#pragma unroll
            for (int j = 0; j < 16; j++) {
                float4 e = er[j];
                d0 = fmaf(x[j].x, e.x, d0);
                d1 = fmaf(x[j].y, e.y, d1);
                d2 = fmaf(x[j].z, e.z, d2);
                d3 = fmaf(x[j].w, e.w, d3);
            }
            float sc = ((d0 + d1) + (d2 + d3)) + g_nh[k];
            unsigned u = __float_as_uint(sc);
            u = (u & 0x80000000u) ? ~u : (u | 0x80000000u);   // monotone map
            unsigned long long kk =
                ((unsigned long long)u << 32) | (unsigned)(~k);
            key = (kk > key) ? kk : key;
        }
#pragma unroll
        for (int m = 16; m >= 1; m >>= 1) {
            unsigned long long ok = __shfl_xor_sync(0xffffffffu, key, m);
            key = (ok > key) ? ok : key;
        }
        if (lane == 0) atomicMax(&g_bm[row], key);
    }
}

// ---------------------------------------------------------------------------
// Combine: 8 threads/row, 2 float4 chunks per thread per stream.
// Rescue winners decoded inline from g_bm (nonzero = rescued).
// ---------------------------------------------------------------------------
__global__ void __launch_bounds__(256)
vq_combine_kernel(const float* __restrict__ inp,
                  const float* __restrict__ emb,
                  float* __restrict__ out) {
    const int t   = blockIdx.x * blockDim.x + threadIdx.x;   // NROWS*8
    const int row = t >> 3;
    const int c   = t & 7;

    const unsigned long long key = g_bm[row];
    const int bi = key ? ((int)(~(unsigned)(key & 0xFFFFFFFFull)) & (KTOT - 1))
                       : g_bi[row];

    const float4* qv = reinterpret_cast<const float4*>(emb + (size_t)bi * D);
    float4* oq = reinterpret_cast<float4*>(out + (size_t)row * D);
    oq[c]     = qv[c];
    oq[c + 8] = qv[c + 8];

    const float4* xi = reinterpret_cast<const float4*>(inp + (size_t)row * D);
    float4* of = reinterpret_cast<float4*>(out + OFF_FLAT + (size_t)row * D);
    of[c]     = xi[c];
    of[c + 8] = xi[c + 8];

    if (c == 0) out[OFF_IDX + row] = (float)bi;
}

// ---------------------------------------------------------------------------
extern "C" void kernel_launch(void* const* d_in, const int* in_sizes, int n_in,
                              void* d_out, int out_size) {
    const float* inp = (const float*)d_in[0];   // [64,32,32,64] fp32
    const float* emb = (const float*)d_in[1];   // [2048,64]     fp32
    float* out = (float*)d_out;

    static int smem_set = 0;
    if (!smem_set) {
        cudaFuncSetAttribute(vq_mma_kernel,
                             cudaFuncAttributeMaxDynamicSharedMemorySize, SMEM_TOTAL);
        smem_set = 1;
    }

    vq_split_e<<<KTOT * 32 / 256, 256>>>(emb);
    vq_mma_kernel<<<NBLOCKS, 256, SMEM_TOTAL>>>(inp);
    vq_merge_kernel<<<NROWS / 256, 256>>>();
    vq_rescue_kernel<<<RES_BLOCKS, 256>>>(inp, emb);
    vq_combine_kernel<<<NROWS * 8 / 256, 256>>>(inp, emb, out);
}